// round 2
// baseline (speedup 1.0000x reference)
#include <cuda_runtime.h>
#include <cstdint>
#include <cstddef>

// ---------------------------------------------------------------------------
// Problem constants (fixed by the reference)
// ---------------------------------------------------------------------------
#define SEQ     512
#define BATCHN  4
#define NH      16
#define DMODEL  1024
#define KDIM    64
#define MFF     4096
#define MEMLEN  3
#define LCTX    2048          // (MEMLEN+1)*SEQ
#define NTOK    2048          // SEQ*BATCHN  (query tokens)
#define NKV     8192          // LCTX*BATCHN (key/value tokens)
#define LN_EPS  1e-5f

// ---------------------------------------------------------------------------
// Scratch (device globals; no allocations allowed anywhere)
// ---------------------------------------------------------------------------
__device__ float g_q [NTOK * DMODEL];
__device__ float g_k [NKV  * DMODEL];
__device__ float g_v [NKV  * DMODEL];
__device__ float g_av[NTOK * DMODEL];
__device__ float g_u0[NTOK * DMODEL];   // pre-LN1 (av @ wc^T)
__device__ float g_u [NTOK * DMODEL];   // LN1 output (FFN input + residual)
__device__ float g_h [NTOK * MFF];      // FFN hidden
__device__ float g_z [NTOK * DMODEL];   // pre-LN2

// ---------------------------------------------------------------------------
// SGEMM (NT): C[M,N] = A[M,K] * B[N,K]^T  (+bias, +relu)
// A rows may be gathered from two source tensors: rows < split come from A,
// rows >= split from A2 (used for the memory||x concat in K/V projection).
// BM=BN=128, BK=8, 256 threads, 8x8 per-thread tile.
// Requires M%128==0, N%128==0, K%8==0 (true for all call sites here).
// EPI: 0 = none, 1 = +bias, 2 = +bias then relu
// ---------------------------------------------------------------------------
template <int EPI>
__global__ __launch_bounds__(256) void sgemm_nt(
    const float* __restrict__ A, const float* __restrict__ A2, int split,
    const float* __restrict__ Bw, const float* __restrict__ bias,
    float* __restrict__ C, int M, int N, int Kd)
{
    constexpr int BM = 128, BN = 128, BK = 8;
    __shared__ float As[BK][BM];
    __shared__ float Bs[BK][BN];

    const int tid = threadIdx.x;
    const int tx  = tid & 15;          // 0..15  -> N direction
    const int ty  = tid >> 4;          // 0..15  -> M direction
    const int bm  = blockIdx.y * BM;
    const int bn  = blockIdx.x * BN;

    // Global-load mapping: each thread loads one float4 per operand per K-tile.
    const int lm = tid >> 1;           // 0..127 : row within tile
    const int lk = (tid & 1) * 4;      // 0 or 4 : k offset

    const int arow = bm + lm;
    const float* Ap = (arow < split) ? (A  + (size_t)arow         * Kd + lk)
                                     : (A2 + (size_t)(arow-split) * Kd + lk);
    const float* Bp = Bw + (size_t)(bn + lm) * Kd + lk;

    float acc[8][8] = {};

    for (int k0 = 0; k0 < Kd; k0 += BK) {
        const float4 a4 = *(const float4*)(Ap + k0);
        const float4 b4 = *(const float4*)(Bp + k0);
        __syncthreads();               // previous tile fully consumed
        As[lk+0][lm] = a4.x; As[lk+1][lm] = a4.y;
        As[lk+2][lm] = a4.z; As[lk+3][lm] = a4.w;
        Bs[lk+0][lm] = b4.x; Bs[lk+1][lm] = b4.y;
        Bs[lk+2][lm] = b4.z; Bs[lk+3][lm] = b4.w;
        __syncthreads();

        #pragma unroll
        for (int kk = 0; kk < BK; kk++) {
            float ar[8], br[8];
            #pragma unroll
            for (int i = 0; i < 8; i++) ar[i] = As[kk][ty*8 + i];
            #pragma unroll
            for (int j = 0; j < 8; j++) br[j] = Bs[kk][tx*8 + j];
            #pragma unroll
            for (int i = 0; i < 8; i++)
                #pragma unroll
                for (int j = 0; j < 8; j++)
                    acc[i][j] = fmaf(ar[i], br[j], acc[i][j]);
        }
    }

    #pragma unroll
    for (int i = 0; i < 8; i++) {
        const int row = bm + ty*8 + i;
        float* crow = C + (size_t)row * N + bn + tx*8;
        #pragma unroll
        for (int j0 = 0; j0 < 8; j0 += 4) {
            float v0 = acc[i][j0+0], v1 = acc[i][j0+1];
            float v2 = acc[i][j0+2], v3 = acc[i][j0+3];
            if (EPI >= 1) {
                const int col = bn + tx*8 + j0;
                v0 += bias[col+0]; v1 += bias[col+1];
                v2 += bias[col+2]; v3 += bias[col+3];
            }
            if (EPI == 2) {
                v0 = fmaxf(v0, 0.f); v1 = fmaxf(v1, 0.f);
                v2 = fmaxf(v2, 0.f); v3 = fmaxf(v3, 0.f);
            }
            *(float4*)(crow + j0) = make_float4(v0, v1, v2, v3);
        }
    }
}

// ---------------------------------------------------------------------------
// Flash attention (online softmax), fp32.
//   q : (S,B,H*K) rows = s*B+b
//   k,v: (L,B,H*K) rows = l*B+b
//   mask: (S, L)
//   av: (S,B,H*K)
// Grid: (SEQ/32, NH*BATCHN). Block 256 threads: 16(tx,N) x 16(ty,M).
// Per block: 32 queries for one (h,b); key tiles of 64; head dim 64.
// Thread tile: 2 queries x 4 cols.
// ---------------------------------------------------------------------------
#define AQ 32
#define AK 64
#define KVP 65                          // smem pitch for K^T / V tiles

__global__ __launch_bounds__(256) void attn_kernel(
    const float* __restrict__ q, const float* __restrict__ k,
    const float* __restrict__ v, const float* __restrict__ mask,
    float* __restrict__ av)
{
    __shared__ float Qs[AQ * KDIM];     // [q][d]   pitch 64
    __shared__ float Ps[AQ * AK];       // [q][key] pitch 64
    __shared__ float KV[KDIM * KVP];    // K as [d][key], then V as [key][d]

    const int tid = threadIdx.x;
    const int tx  = tid & 15;
    const int ty  = tid >> 4;
    const int h   = blockIdx.y >> 2;
    const int b   = blockIdx.y & 3;
    const int s0  = blockIdx.x * AQ;
    const int q0  = ty * 2;
    const unsigned FULL = 0xffffffffu;

    // Load Q tile (32 x 64 floats)
    #pragma unroll
    for (int r = 0; r < 2; r++) {
        const int lin = tid + r * 256;        // 0..511
        const int qq  = lin >> 4;
        const int d4  = (lin & 15) * 4;
        const float4 t = *(const float4*)&q[(size_t)((s0+qq)*BATCHN + b)*DMODEL + h*KDIM + d4];
        *(float4*)&Qs[qq*KDIM + d4] = t;
    }

    float mi[2] = {-1e30f, -1e30f};
    float li[2] = {0.f, 0.f};
    float oa[2][4] = {};

    for (int l0 = 0; l0 < LCTX; l0 += AK) {
        __syncthreads();                       // KV free (prev PV done); Qs visible
        // K tile, transposed: KV[d*KVP + key]
        #pragma unroll
        for (int r = 0; r < 4; r++) {
            const int lin = tid + r * 256;     // 0..1023
            const int key = lin >> 4;
            const int d4  = (lin & 15) * 4;
            const float4 t = *(const float4*)&k[(size_t)((l0+key)*BATCHN + b)*DMODEL + h*KDIM + d4];
            KV[(d4+0)*KVP + key] = t.x;
            KV[(d4+1)*KVP + key] = t.y;
            KV[(d4+2)*KVP + key] = t.z;
            KV[(d4+3)*KVP + key] = t.w;
        }
        __syncthreads();

        // S = Q K^T   (thread: 2 queries x 4 keys)
        float s[2][4] = {};
        #pragma unroll 8
        for (int d = 0; d < KDIM; d++) {
            const float a0 = Qs[(q0+0)*KDIM + d];
            const float a1 = Qs[(q0+1)*KDIM + d];
            #pragma unroll
            for (int j = 0; j < 4; j++) {
                const float bb = KV[d*KVP + tx*4 + j];
                s[0][j] = fmaf(a0, bb, s[0][j]);
                s[1][j] = fmaf(a1, bb, s[1][j]);
            }
        }

        // scale + mask, online softmax update
        #pragma unroll
        for (int i = 0; i < 2; i++) {
            const float* mrow = mask + (size_t)(s0+q0+i)*LCTX + l0 + tx*4;
            float tm = -1e30f;
            #pragma unroll
            for (int j = 0; j < 4; j++) {
                s[i][j] = s[i][j] * 0.125f + mrow[j];
                tm = fmaxf(tm, s[i][j]);
            }
            #pragma unroll
            for (int m = 8; m > 0; m >>= 1)
                tm = fmaxf(tm, __shfl_xor_sync(FULL, tm, m));
            const float mnew = fmaxf(mi[i], tm);
            const float corr = __expf(mi[i] - mnew);
            float p[4], rs = 0.f;
            #pragma unroll
            for (int j = 0; j < 4; j++) { p[j] = __expf(s[i][j] - mnew); rs += p[j]; }
            *(float4*)&Ps[(q0+i)*AK + tx*4] = make_float4(p[0], p[1], p[2], p[3]);
            #pragma unroll
            for (int m = 8; m > 0; m >>= 1)
                rs += __shfl_xor_sync(FULL, rs, m);
            li[i] = li[i] * corr + rs;
            mi[i] = mnew;
            #pragma unroll
            for (int j = 0; j < 4; j++) oa[i][j] *= corr;
        }
        __syncthreads();                       // Ps visible; K reads done

        // V tile: KV[key*KVP + d]
        #pragma unroll
        for (int r = 0; r < 4; r++) {
            const int lin = tid + r * 256;
            const int key = lin >> 4;
            const int d4  = (lin & 15) * 4;
            const float4 t = *(const float4*)&v[(size_t)((l0+key)*BATCHN + b)*DMODEL + h*KDIM + d4];
            KV[key*KVP + d4+0] = t.x;
            KV[key*KVP + d4+1] = t.y;
            KV[key*KVP + d4+2] = t.z;
            KV[key*KVP + d4+3] = t.w;
        }
        __syncthreads();

        // O += P V   (thread: 2 queries x 4 dims)
        #pragma unroll 8
        for (int kk = 0; kk < AK; kk++) {
            const float a0 = Ps[(q0+0)*AK + kk];
            const float a1 = Ps[(q0+1)*AK + kk];
            #pragma unroll
            for (int j = 0; j < 4; j++) {
                const float bb = KV[kk*KVP + tx*4 + j];
                oa[0][j] = fmaf(a0, bb, oa[0][j]);
                oa[1][j] = fmaf(a1, bb, oa[1][j]);
            }
        }
    }

    #pragma unroll
    for (int i = 0; i < 2; i++) {
        const float inv = 1.f / li[i];
        float* orow = av + (size_t)((s0+q0+i)*BATCHN + b)*DMODEL + h*KDIM + tx*4;
        orow[0] = oa[i][0] * inv;
        orow[1] = oa[i][1] * inv;
        orow[2] = oa[i][2] * inv;
        orow[3] = oa[i][3] * inv;
    }
}

// ---------------------------------------------------------------------------
// Fused residual + LayerNorm: out[row] = LN(a[row] + r[row]) * gamma + beta
// One block (256 threads) per row of 1024.
// ---------------------------------------------------------------------------
__global__ __launch_bounds__(256) void ln_kernel(
    const float* __restrict__ a, const float* __restrict__ r,
    const float* __restrict__ gamma, const float* __restrict__ beta,
    float* __restrict__ out)
{
    __shared__ float red[2][8];
    const int row = blockIdx.x;
    const int tid = threadIdx.x;
    const float* pa = a + (size_t)row * DMODEL;
    const float* pr = r + (size_t)row * DMODEL;

    float vl[4];
    float s = 0.f, s2 = 0.f;
    #pragma unroll
    for (int i = 0; i < 4; i++) {
        const int c = tid + i * 256;
        const float xv = pa[c] + pr[c];
        vl[i] = xv;
        s += xv;
        s2 = fmaf(xv, xv, s2);
    }
    #pragma unroll
    for (int m = 16; m > 0; m >>= 1) {
        s  += __shfl_xor_sync(0xffffffffu, s,  m);
        s2 += __shfl_xor_sync(0xffffffffu, s2, m);
    }
    if ((tid & 31) == 0) { red[0][tid >> 5] = s; red[1][tid >> 5] = s2; }
    __syncthreads();
    if (tid == 0) {
        float a0 = 0.f, b0 = 0.f;
        #pragma unroll
        for (int w = 0; w < 8; w++) { a0 += red[0][w]; b0 += red[1][w]; }
        red[0][0] = a0; red[1][0] = b0;
    }
    __syncthreads();
    const float mu  = red[0][0] * (1.f / DMODEL);
    const float var = red[1][0] * (1.f / DMODEL) - mu * mu;
    const float inv = rsqrtf(var + LN_EPS);

    float* po = out + (size_t)row * DMODEL;
    #pragma unroll
    for (int i = 0; i < 4; i++) {
        const int c = tid + i * 256;
        po[c] = (vl[i] - mu) * inv * gamma[c] + beta[c];
    }
}

// ---------------------------------------------------------------------------
// Launch
// Inputs (metadata order):
// 0 x, 1 mask, 2 memory, 3 heads(int, unused), 4 wq, 5 wk, 6 wv, 7 wc,
// 8 w1, 9 b1, 10 w2, 11 b2, 12 ln1_g, 13 ln1_b, 14 ln2_g, 15 ln2_b
// ---------------------------------------------------------------------------
extern "C" void kernel_launch(void* const* d_in, const int* in_sizes, int n_in,
                              void* d_out, int out_size)
{
    const float* x    = (const float*)d_in[0];
    const float* mask = (const float*)d_in[1];
    const float* mem  = (const float*)d_in[2];
    const float* wq   = (const float*)d_in[4];
    const float* wk   = (const float*)d_in[5];
    const float* wv   = (const float*)d_in[6];
    const float* wc   = (const float*)d_in[7];
    const float* w1   = (const float*)d_in[8];
    const float* b1   = (const float*)d_in[9];
    const float* w2   = (const float*)d_in[10];
    const float* b2   = (const float*)d_in[11];
    const float* g1   = (const float*)d_in[12];
    const float* be1  = (const float*)d_in[13];
    const float* g2   = (const float*)d_in[14];
    const float* be2  = (const float*)d_in[15];
    float* out = (float*)d_out;

    float *q, *k, *v, *avp, *u0, *u, *hh, *z;
    cudaGetSymbolAddress((void**)&q,   g_q);
    cudaGetSymbolAddress((void**)&k,   g_k);
    cudaGetSymbolAddress((void**)&v,   g_v);
    cudaGetSymbolAddress((void**)&avp, g_av);
    cudaGetSymbolAddress((void**)&u0,  g_u0);
    cudaGetSymbolAddress((void**)&u,   g_u);
    cudaGetSymbolAddress((void**)&hh,  g_h);
    cudaGetSymbolAddress((void**)&z,   g_z);

    const dim3 blk(256);
    const int splitKV = MEMLEN * SEQ * BATCHN;   // 6144 rows from memory, rest from x

    // Projections
    sgemm_nt<0><<<dim3(DMODEL/128, NTOK/128), blk>>>(x,   x, NTOK,    wq, nullptr, q, NTOK, DMODEL, DMODEL);
    sgemm_nt<0><<<dim3(DMODEL/128, NKV /128), blk>>>(mem, x, splitKV, wk, nullptr, k, NKV,  DMODEL, DMODEL);
    sgemm_nt<0><<<dim3(DMODEL/128, NKV /128), blk>>>(mem, x, splitKV, wv, nullptr, v, NKV,  DMODEL, DMODEL);

    // Attention
    attn_kernel<<<dim3(SEQ/AQ, NH*BATCHN), blk>>>(q, k, v, mask, avp);

    // Output projection + LN1(residual x)
    sgemm_nt<0><<<dim3(DMODEL/128, NTOK/128), blk>>>(avp, avp, NTOK, wc, nullptr, u0, NTOK, DMODEL, DMODEL);
    ln_kernel<<<NTOK, blk>>>(u0, x, g1, be1, u);

    // FFN
    sgemm_nt<2><<<dim3(MFF   /128, NTOK/128), blk>>>(u,  u,  NTOK, w1, b1, hh, NTOK, MFF,    DMODEL);
    sgemm_nt<1><<<dim3(DMODEL/128, NTOK/128), blk>>>(hh, hh, NTOK, w2, b2, z,  NTOK, DMODEL, MFF);

    // LN2(residual u) -> output
    ln_kernel<<<NTOK, blk>>>(z, u, g2, be2, out);
}

// round 4
// speedup vs baseline: 1.8052x; 1.8052x over previous
#include <cuda_runtime.h>
#include <cstdint>
#include <cstddef>

// ---------------------------------------------------------------------------
// Problem constants
// ---------------------------------------------------------------------------
#define SEQ     512
#define BATCHN  4
#define NH      16
#define DMODEL  1024
#define KDIM    64
#define MFF     4096
#define MEMLEN  3
#define LCTX    2048
#define NTOK    2048
#define NKV     8192
#define LN_EPS  1e-5f

// ---------------------------------------------------------------------------
// Scratch
// ---------------------------------------------------------------------------
__device__ float g_q [NTOK * DMODEL];
__device__ float g_k [NKV  * DMODEL];
__device__ float g_v [NKV  * DMODEL];
__device__ float g_av[NTOK * DMODEL];
__device__ float g_u0[NTOK * DMODEL];
__device__ float g_u [NTOK * DMODEL];
__device__ float g_h [NTOK * MFF];
__device__ float g_z [NTOK * DMODEL];

// ---------------------------------------------------------------------------
// TF32 helpers
// ---------------------------------------------------------------------------
__device__ __forceinline__ uint32_t to_tf32(float x) {
    uint32_t r;
    asm("cvt.rna.tf32.f32 %0, %1;" : "=r"(r) : "f"(x));
    return r;
}

__device__ __forceinline__ void mma_tf32(
    float& d0, float& d1, float& d2, float& d3,
    uint32_t a0, uint32_t a1, uint32_t a2, uint32_t a3,
    uint32_t b0, uint32_t b1)
{
    asm volatile(
        "mma.sync.aligned.m16n8k8.row.col.f32.tf32.tf32.f32 "
        "{%0,%1,%2,%3},{%4,%5,%6,%7},{%8,%9},{%0,%1,%2,%3};"
        : "+f"(d0), "+f"(d1), "+f"(d2), "+f"(d3)
        : "r"(a0), "r"(a1), "r"(a2), "r"(a3), "r"(b0), "r"(b1));
}

// ---------------------------------------------------------------------------
// TF32 tensor-core GEMM (NT): C[M,N] = A[M,K] * B[N,K]^T  (+bias, +relu)
// A rows gathered from A (row<split) or A2 (row>=split).
// BM=BN=128, BK=16, 256 threads (8 warps), warp tile 64x32 (4x4 m16n8k8).
// Requires M%128==0, N%128==0, K%16==0.
// EPI: 0 none, 1 +bias, 2 +bias+relu
// ---------------------------------------------------------------------------
#define GP 20   // smem pitch (floats): g*20+t mod 32 hits all 32 banks

template <int EPI>
__global__ __launch_bounds__(256) void gemm_tf32(
    const float* __restrict__ A, const float* __restrict__ A2, int split,
    const float* __restrict__ Bw, const float* __restrict__ bias,
    float* __restrict__ C, int M, int N, int Kd)
{
    constexpr int BM = 128, BN = 128, BK = 16;
    __shared__ uint32_t As[BM][GP];
    __shared__ uint32_t Bs[BN][GP];

    const int tid  = threadIdx.x;
    const int lane = tid & 31;
    const int w    = tid >> 5;          // 0..7
    const int wm   = (w >> 2) * 64;     // warp M origin within tile
    const int wn   = (w & 3) * 32;      // warp N origin within tile
    const int g    = lane >> 2;         // 0..7
    const int t    = lane & 3;          // 0..3

    const int bm = blockIdx.y * BM;
    const int bn = blockIdx.x * BN;

    // Global-load mapping: 2 float4 per thread per operand per BK-tile.
    const int r0  = tid >> 2;            // rows for i=0 : 0..63
    const int r1  = r0 + 64;             // rows for i=1 : 64..127
    const int kq  = (tid & 3) * 4;

    const int arow0 = bm + r0, arow1 = bm + r1;
    const float* Ap0 = (arow0 < split) ? (A + (size_t)arow0 * Kd) : (A2 + (size_t)(arow0 - split) * Kd);
    const float* Ap1 = (arow1 < split) ? (A + (size_t)arow1 * Kd) : (A2 + (size_t)(arow1 - split) * Kd);
    const float* Bp0 = Bw + (size_t)(bn + r0) * Kd;
    const float* Bp1 = Bw + (size_t)(bn + r1) * Kd;

    float acc[4][4][4] = {};

    for (int k0 = 0; k0 < Kd; k0 += BK) {
        const float4 a40 = *(const float4*)(Ap0 + k0 + kq);
        const float4 a41 = *(const float4*)(Ap1 + k0 + kq);
        const float4 b40 = *(const float4*)(Bp0 + k0 + kq);
        const float4 b41 = *(const float4*)(Bp1 + k0 + kq);
        __syncthreads();                 // previous tile fully consumed
        As[r0][kq+0] = to_tf32(a40.x); As[r0][kq+1] = to_tf32(a40.y);
        As[r0][kq+2] = to_tf32(a40.z); As[r0][kq+3] = to_tf32(a40.w);
        As[r1][kq+0] = to_tf32(a41.x); As[r1][kq+1] = to_tf32(a41.y);
        As[r1][kq+2] = to_tf32(a41.z); As[r1][kq+3] = to_tf32(a41.w);
        Bs[r0][kq+0] = to_tf32(b40.x); Bs[r0][kq+1] = to_tf32(b40.y);
        Bs[r0][kq+2] = to_tf32(b40.z); Bs[r0][kq+3] = to_tf32(b40.w);
        Bs[r1][kq+0] = to_tf32(b41.x); Bs[r1][kq+1] = to_tf32(b41.y);
        Bs[r1][kq+2] = to_tf32(b41.z); Bs[r1][kq+3] = to_tf32(b41.w);
        __syncthreads();

        #pragma unroll
        for (int ks = 0; ks < 2; ks++) {
            const int kb = ks * 8 + t;
            uint32_t af[4][4];
            #pragma unroll
            for (int mt = 0; mt < 4; mt++) {
                const int row = wm + mt * 16 + g;
                af[mt][0] = As[row    ][kb    ];
                af[mt][1] = As[row + 8][kb    ];
                af[mt][2] = As[row    ][kb + 4];
                af[mt][3] = As[row + 8][kb + 4];
            }
            uint32_t bf[4][2];
            #pragma unroll
            for (int nt = 0; nt < 4; nt++) {
                const int n = wn + nt * 8 + g;
                bf[nt][0] = Bs[n][kb    ];
                bf[nt][1] = Bs[n][kb + 4];
            }
            #pragma unroll
            for (int mt = 0; mt < 4; mt++)
                #pragma unroll
                for (int nt = 0; nt < 4; nt++)
                    mma_tf32(acc[mt][nt][0], acc[mt][nt][1], acc[mt][nt][2], acc[mt][nt][3],
                             af[mt][0], af[mt][1], af[mt][2], af[mt][3],
                             bf[nt][0], bf[nt][1]);
        }
    }

    // Epilogue. Accum layout (m16n8): c0,c1 at (g, 2t),(g, 2t+1); c2,c3 at (g+8, ...)
    #pragma unroll
    for (int mt = 0; mt < 4; mt++) {
        const int row0 = bm + wm + mt * 16 + g;
        #pragma unroll
        for (int nt = 0; nt < 4; nt++) {
            const int col = bn + wn + nt * 8 + 2 * t;
            float v0 = acc[mt][nt][0], v1 = acc[mt][nt][1];
            float v2 = acc[mt][nt][2], v3 = acc[mt][nt][3];
            if (EPI >= 1) {
                const float bb0 = bias[col], bb1 = bias[col + 1];
                v0 += bb0; v1 += bb1; v2 += bb0; v3 += bb1;
            }
            if (EPI == 2) {
                v0 = fmaxf(v0, 0.f); v1 = fmaxf(v1, 0.f);
                v2 = fmaxf(v2, 0.f); v3 = fmaxf(v3, 0.f);
            }
            *(float2*)&C[(size_t)row0 * N + col]       = make_float2(v0, v1);
            *(float2*)&C[(size_t)(row0 + 8) * N + col] = make_float2(v2, v3);
        }
    }
}

// ---------------------------------------------------------------------------
// Flash attention (online softmax), fp32. Unchanged from R2 baseline.
// ---------------------------------------------------------------------------
#define AQ 32
#define AK 64
#define KVP 65

__global__ __launch_bounds__(256) void attn_kernel(
    const float* __restrict__ q, const float* __restrict__ k,
    const float* __restrict__ v, const float* __restrict__ mask,
    float* __restrict__ av)
{
    __shared__ float Qs[AQ * KDIM];
    __shared__ float Ps[AQ * AK];
    __shared__ float KV[KDIM * KVP];

    const int tid = threadIdx.x;
    const int tx  = tid & 15;
    const int ty  = tid >> 4;
    const int h   = blockIdx.y >> 2;
    const int b   = blockIdx.y & 3;
    const int s0  = blockIdx.x * AQ;
    const int q0  = ty * 2;
    const unsigned FULL = 0xffffffffu;

    #pragma unroll
    for (int r = 0; r < 2; r++) {
        const int lin = tid + r * 256;
        const int qq  = lin >> 4;
        const int d4  = (lin & 15) * 4;
        const float4 tq = *(const float4*)&q[(size_t)((s0+qq)*BATCHN + b)*DMODEL + h*KDIM + d4];
        *(float4*)&Qs[qq*KDIM + d4] = tq;
    }

    float mi[2] = {-1e30f, -1e30f};
    float li[2] = {0.f, 0.f};
    float oa[2][4] = {};

    for (int l0 = 0; l0 < LCTX; l0 += AK) {
        __syncthreads();
        #pragma unroll
        for (int r = 0; r < 4; r++) {
            const int lin = tid + r * 256;
            const int key = lin >> 4;
            const int d4  = (lin & 15) * 4;
            const float4 tk = *(const float4*)&k[(size_t)((l0+key)*BATCHN + b)*DMODEL + h*KDIM + d4];
            KV[(d4+0)*KVP + key] = tk.x;
            KV[(d4+1)*KVP + key] = tk.y;
            KV[(d4+2)*KVP + key] = tk.z;
            KV[(d4+3)*KVP + key] = tk.w;
        }
        __syncthreads();

        float s[2][4] = {};
        #pragma unroll 8
        for (int d = 0; d < KDIM; d++) {
            const float a0 = Qs[(q0+0)*KDIM + d];
            const float a1 = Qs[(q0+1)*KDIM + d];
            #pragma unroll
            for (int j = 0; j < 4; j++) {
                const float bb = KV[d*KVP + tx*4 + j];
                s[0][j] = fmaf(a0, bb, s[0][j]);
                s[1][j] = fmaf(a1, bb, s[1][j]);
            }
        }

        #pragma unroll
        for (int i = 0; i < 2; i++) {
            const float* mrow = mask + (size_t)(s0+q0+i)*LCTX + l0 + tx*4;
            float tm = -1e30f;
            #pragma unroll
            for (int j = 0; j < 4; j++) {
                s[i][j] = s[i][j] * 0.125f + mrow[j];
                tm = fmaxf(tm, s[i][j]);
            }
            #pragma unroll
            for (int m = 8; m > 0; m >>= 1)
                tm = fmaxf(tm, __shfl_xor_sync(FULL, tm, m));
            const float mnew = fmaxf(mi[i], tm);
            const float corr = __expf(mi[i] - mnew);
            float p[4], rs = 0.f;
            #pragma unroll
            for (int j = 0; j < 4; j++) { p[j] = __expf(s[i][j] - mnew); rs += p[j]; }
            *(float4*)&Ps[(q0+i)*AK + tx*4] = make_float4(p[0], p[1], p[2], p[3]);
            #pragma unroll
            for (int m = 8; m > 0; m >>= 1)
                rs += __shfl_xor_sync(FULL, rs, m);
            li[i] = li[i] * corr + rs;
            mi[i] = mnew;
            #pragma unroll
            for (int j = 0; j < 4; j++) oa[i][j] *= corr;
        }
        __syncthreads();

        #pragma unroll
        for (int r = 0; r < 4; r++) {
            const int lin = tid + r * 256;
            const int key = lin >> 4;
            const int d4  = (lin & 15) * 4;
            const float4 tv = *(const float4*)&v[(size_t)((l0+key)*BATCHN + b)*DMODEL + h*KDIM + d4];
            KV[key*KVP + d4+0] = tv.x;
            KV[key*KVP + d4+1] = tv.y;
            KV[key*KVP + d4+2] = tv.z;
            KV[key*KVP + d4+3] = tv.w;
        }
        __syncthreads();

        #pragma unroll 8
        for (int kk = 0; kk < AK; kk++) {
            const float a0 = Ps[(q0+0)*AK + kk];
            const float a1 = Ps[(q0+1)*AK + kk];
            #pragma unroll
            for (int j = 0; j < 4; j++) {
                const float bb = KV[kk*KVP + tx*4 + j];
                oa[0][j] = fmaf(a0, bb, oa[0][j]);
                oa[1][j] = fmaf(a1, bb, oa[1][j]);
            }
        }
    }

    #pragma unroll
    for (int i = 0; i < 2; i++) {
        const float inv = 1.f / li[i];
        float* orow = av + (size_t)((s0+q0+i)*BATCHN + b)*DMODEL + h*KDIM + tx*4;
        orow[0] = oa[i][0] * inv;
        orow[1] = oa[i][1] * inv;
        orow[2] = oa[i][2] * inv;
        orow[3] = oa[i][3] * inv;
    }
}

// ---------------------------------------------------------------------------
// Fused residual + LayerNorm
// ---------------------------------------------------------------------------
__global__ __launch_bounds__(256) void ln_kernel(
    const float* __restrict__ a, const float* __restrict__ r,
    const float* __restrict__ gamma, const float* __restrict__ beta,
    float* __restrict__ out)
{
    __shared__ float red[2][8];
    const int row = blockIdx.x;
    const int tid = threadIdx.x;
    const float* pa = a + (size_t)row * DMODEL;
    const float* pr = r + (size_t)row * DMODEL;

    float vl[4];
    float s = 0.f, s2 = 0.f;
    #pragma unroll
    for (int i = 0; i < 4; i++) {
        const int c = tid + i * 256;
        const float xv = pa[c] + pr[c];
        vl[i] = xv;
        s += xv;
        s2 = fmaf(xv, xv, s2);
    }
    #pragma unroll
    for (int m = 16; m > 0; m >>= 1) {
        s  += __shfl_xor_sync(0xffffffffu, s,  m);
        s2 += __shfl_xor_sync(0xffffffffu, s2, m);
    }
    if ((tid & 31) == 0) { red[0][tid >> 5] = s; red[1][tid >> 5] = s2; }
    __syncthreads();
    if (tid == 0) {
        float a0 = 0.f, b0 = 0.f;
        #pragma unroll
        for (int ww = 0; ww < 8; ww++) { a0 += red[0][ww]; b0 += red[1][ww]; }
        red[0][0] = a0; red[1][0] = b0;
    }
    __syncthreads();
    const float mu  = red[0][0] * (1.f / DMODEL);
    const float var = red[1][0] * (1.f / DMODEL) - mu * mu;
    const float inv = rsqrtf(var + LN_EPS);

    float* po = out + (size_t)row * DMODEL;
    #pragma unroll
    for (int i = 0; i < 4; i++) {
        const int c = tid + i * 256;
        po[c] = (vl[i] - mu) * inv * gamma[c] + beta[c];
    }
}

// ---------------------------------------------------------------------------
// Launch
// ---------------------------------------------------------------------------
extern "C" void kernel_launch(void* const* d_in, const int* in_sizes, int n_in,
                              void* d_out, int out_size)
{
    const float* x    = (const float*)d_in[0];
    const float* mask = (const float*)d_in[1];
    const float* mem  = (const float*)d_in[2];
    const float* wq   = (const float*)d_in[4];
    const float* wk   = (const float*)d_in[5];
    const float* wv   = (const float*)d_in[6];
    const float* wc   = (const float*)d_in[7];
    const float* w1   = (const float*)d_in[8];
    const float* b1   = (const float*)d_in[9];
    const float* w2   = (const float*)d_in[10];
    const float* b2   = (const float*)d_in[11];
    const float* g1   = (const float*)d_in[12];
    const float* be1  = (const float*)d_in[13];
    const float* g2   = (const float*)d_in[14];
    const float* be2  = (const float*)d_in[15];
    float* out = (float*)d_out;

    float *q, *k, *v, *avp, *u0, *u, *hh, *z;
    cudaGetSymbolAddress((void**)&q,   g_q);
    cudaGetSymbolAddress((void**)&k,   g_k);
    cudaGetSymbolAddress((void**)&v,   g_v);
    cudaGetSymbolAddress((void**)&avp, g_av);
    cudaGetSymbolAddress((void**)&u0,  g_u0);
    cudaGetSymbolAddress((void**)&u,   g_u);
    cudaGetSymbolAddress((void**)&hh,  g_h);
    cudaGetSymbolAddress((void**)&z,   g_z);

    const dim3 blk(256);
    const int splitKV = MEMLEN * SEQ * BATCHN;

    gemm_tf32<0><<<dim3(DMODEL/128, NTOK/128), blk>>>(x,   x, NTOK,    wq, nullptr, q, NTOK, DMODEL, DMODEL);
    gemm_tf32<0><<<dim3(DMODEL/128, NKV /128), blk>>>(mem, x, splitKV, wk, nullptr, k, NKV,  DMODEL, DMODEL);
    gemm_tf32<0><<<dim3(DMODEL/128, NKV /128), blk>>>(mem, x, splitKV, wv, nullptr, v, NKV,  DMODEL, DMODEL);

    attn_kernel<<<dim3(SEQ/AQ, NH*BATCHN), blk>>>(q, k, v, mask, avp);

    gemm_tf32<0><<<dim3(DMODEL/128, NTOK/128), blk>>>(avp, avp, NTOK, wc, nullptr, u0, NTOK, DMODEL, DMODEL);
    ln_kernel<<<NTOK, blk>>>(u0, x, g1, be1, u);

    gemm_tf32<2><<<dim3(MFF   /128, NTOK/128), blk>>>(u,  u,  NTOK, w1, b1, hh, NTOK, MFF,    DMODEL);
    gemm_tf32<1><<<dim3(DMODEL/128, NTOK/128), blk>>>(hh, hh, NTOK, w2, b2, z,  NTOK, DMODEL, MFF);

    ln_kernel<<<NTOK, blk>>>(z, u, g2, be2, out);
}

// round 5
// speedup vs baseline: 3.0293x; 1.6781x over previous
#include <cuda_runtime.h>
#include <cstdint>
#include <cstddef>

// ---------------------------------------------------------------------------
// Problem constants
// ---------------------------------------------------------------------------
#define SEQ     512
#define BATCHN  4
#define NH      16
#define DMODEL  1024
#define KDIM    64
#define MFF     4096
#define MEMLEN  3
#define LCTX    2048
#define NTOK    2048
#define NKV     8192
#define LN_EPS  1e-5f

// ---------------------------------------------------------------------------
// Scratch
// ---------------------------------------------------------------------------
__device__ float g_q [NTOK * DMODEL];
__device__ float g_k [NKV  * DMODEL];
__device__ float g_v [NKV  * DMODEL];
__device__ float g_av[NTOK * DMODEL];
__device__ float g_u0[NTOK * DMODEL];
__device__ float g_u [NTOK * DMODEL];
__device__ float g_h [NTOK * MFF];
__device__ float g_z [NTOK * DMODEL];

// ---------------------------------------------------------------------------
// TF32 helpers
// ---------------------------------------------------------------------------
__device__ __forceinline__ uint32_t to_tf32(float x) {
    uint32_t r;
    asm("cvt.rna.tf32.f32 %0, %1;" : "=r"(r) : "f"(x));
    return r;
}

__device__ __forceinline__ void mma_tf32(
    float& d0, float& d1, float& d2, float& d3,
    uint32_t a0, uint32_t a1, uint32_t a2, uint32_t a3,
    uint32_t b0, uint32_t b1)
{
    asm volatile(
        "mma.sync.aligned.m16n8k8.row.col.f32.tf32.tf32.f32 "
        "{%0,%1,%2,%3},{%4,%5,%6,%7},{%8,%9},{%0,%1,%2,%3};"
        : "+f"(d0), "+f"(d1), "+f"(d2), "+f"(d3)
        : "r"(a0), "r"(a1), "r"(a2), "r"(a3), "r"(b0), "r"(b1));
}

// ---------------------------------------------------------------------------
// TF32 tensor-core GEMM (NT): C[M,N] = A[M,K] * B[N,K]^T  (+bias, +relu)
// Unchanged from R4 (passing, 91 TF/s).
// ---------------------------------------------------------------------------
#define GP 20

template <int EPI>
__global__ __launch_bounds__(256) void gemm_tf32(
    const float* __restrict__ A, const float* __restrict__ A2, int split,
    const float* __restrict__ Bw, const float* __restrict__ bias,
    float* __restrict__ C, int M, int N, int Kd)
{
    constexpr int BM = 128, BN = 128, BK = 16;
    __shared__ uint32_t As[BM][GP];
    __shared__ uint32_t Bs[BN][GP];

    const int tid  = threadIdx.x;
    const int lane = tid & 31;
    const int w    = tid >> 5;
    const int wm   = (w >> 2) * 64;
    const int wn   = (w & 3) * 32;
    const int g    = lane >> 2;
    const int t    = lane & 3;

    const int bm = blockIdx.y * BM;
    const int bn = blockIdx.x * BN;

    const int r0  = tid >> 2;
    const int r1  = r0 + 64;
    const int kq  = (tid & 3) * 4;

    const int arow0 = bm + r0, arow1 = bm + r1;
    const float* Ap0 = (arow0 < split) ? (A + (size_t)arow0 * Kd) : (A2 + (size_t)(arow0 - split) * Kd);
    const float* Ap1 = (arow1 < split) ? (A + (size_t)arow1 * Kd) : (A2 + (size_t)(arow1 - split) * Kd);
    const float* Bp0 = Bw + (size_t)(bn + r0) * Kd;
    const float* Bp1 = Bw + (size_t)(bn + r1) * Kd;

    float acc[4][4][4] = {};

    for (int k0 = 0; k0 < Kd; k0 += BK) {
        const float4 a40 = *(const float4*)(Ap0 + k0 + kq);
        const float4 a41 = *(const float4*)(Ap1 + k0 + kq);
        const float4 b40 = *(const float4*)(Bp0 + k0 + kq);
        const float4 b41 = *(const float4*)(Bp1 + k0 + kq);
        __syncthreads();
        As[r0][kq+0] = to_tf32(a40.x); As[r0][kq+1] = to_tf32(a40.y);
        As[r0][kq+2] = to_tf32(a40.z); As[r0][kq+3] = to_tf32(a40.w);
        As[r1][kq+0] = to_tf32(a41.x); As[r1][kq+1] = to_tf32(a41.y);
        As[r1][kq+2] = to_tf32(a41.z); As[r1][kq+3] = to_tf32(a41.w);
        Bs[r0][kq+0] = to_tf32(b40.x); Bs[r0][kq+1] = to_tf32(b40.y);
        Bs[r0][kq+2] = to_tf32(b40.z); Bs[r0][kq+3] = to_tf32(b40.w);
        Bs[r1][kq+0] = to_tf32(b41.x); Bs[r1][kq+1] = to_tf32(b41.y);
        Bs[r1][kq+2] = to_tf32(b41.z); Bs[r1][kq+3] = to_tf32(b41.w);
        __syncthreads();

        #pragma unroll
        for (int ks = 0; ks < 2; ks++) {
            const int kb = ks * 8 + t;
            uint32_t af[4][4];
            #pragma unroll
            for (int mt = 0; mt < 4; mt++) {
                const int row = wm + mt * 16 + g;
                af[mt][0] = As[row    ][kb    ];
                af[mt][1] = As[row + 8][kb    ];
                af[mt][2] = As[row    ][kb + 4];
                af[mt][3] = As[row + 8][kb + 4];
            }
            uint32_t bf[4][2];
            #pragma unroll
            for (int nt = 0; nt < 4; nt++) {
                const int n = wn + nt * 8 + g;
                bf[nt][0] = Bs[n][kb    ];
                bf[nt][1] = Bs[n][kb + 4];
            }
            #pragma unroll
            for (int mt = 0; mt < 4; mt++)
                #pragma unroll
                for (int nt = 0; nt < 4; nt++)
                    mma_tf32(acc[mt][nt][0], acc[mt][nt][1], acc[mt][nt][2], acc[mt][nt][3],
                             af[mt][0], af[mt][1], af[mt][2], af[mt][3],
                             bf[nt][0], bf[nt][1]);
        }
    }

    #pragma unroll
    for (int mt = 0; mt < 4; mt++) {
        const int row0 = bm + wm + mt * 16 + g;
        #pragma unroll
        for (int nt = 0; nt < 4; nt++) {
            const int col = bn + wn + nt * 8 + 2 * t;
            float v0 = acc[mt][nt][0], v1 = acc[mt][nt][1];
            float v2 = acc[mt][nt][2], v3 = acc[mt][nt][3];
            if (EPI >= 1) {
                const float bb0 = bias[col], bb1 = bias[col + 1];
                v0 += bb0; v1 += bb1; v2 += bb0; v3 += bb1;
            }
            if (EPI == 2) {
                v0 = fmaxf(v0, 0.f); v1 = fmaxf(v1, 0.f);
                v2 = fmaxf(v2, 0.f); v3 = fmaxf(v3, 0.f);
            }
            *(float2*)&C[(size_t)row0 * N + col]       = make_float2(v0, v1);
            *(float2*)&C[(size_t)(row0 + 8) * N + col] = make_float2(v2, v3);
        }
    }
}

// ---------------------------------------------------------------------------
// Flash attention on tf32 tensor cores.
// Block: 128 queries of one (h,b). 8 warps, each warp = 16 query rows.
// Key tiles of 64. Q held in registers as A-fragments.
// K,V tiles in smem [key][dim] tf32, pitch 68 (conflict-free QK B reads).
// P stays in registers; S-layout -> A-fragment permutation done via shfl.
// ---------------------------------------------------------------------------
#define KP 68

__global__ __launch_bounds__(256) void attn_mma(
    const float* __restrict__ q, const float* __restrict__ k,
    const float* __restrict__ v, const float* __restrict__ mask,
    float* __restrict__ av)
{
    __shared__ uint32_t Ks[64][KP];
    __shared__ uint32_t Vs[64][KP];

    const int tid  = threadIdx.x;
    const int lane = tid & 31;
    const int w    = tid >> 5;
    const int g    = lane >> 2;
    const int t    = lane & 3;
    const int h    = blockIdx.y >> 2;
    const int b    = blockIdx.y & 3;
    const int s0   = blockIdx.x * 128;
    const int row0 = s0 + w * 16 + g;      // this thread's first query row
    const unsigned FULL = 0xffffffffu;

    // Q fragments (A operand), loaded once: a0=Q[g][8ks+t], a1=Q[g+8][..],
    // a2=Q[g][8ks+t+4], a3=Q[g+8][..+4]
    uint32_t qa[8][4];
    {
        const size_t off0 = (size_t)(row0      * BATCHN + b) * DMODEL + h * KDIM;
        const size_t off8 = (size_t)((row0 + 8)* BATCHN + b) * DMODEL + h * KDIM;
        #pragma unroll
        for (int ks = 0; ks < 8; ks++) {
            const int d0 = ks * 8 + t;
            qa[ks][0] = to_tf32(q[off0 + d0]);
            qa[ks][1] = to_tf32(q[off8 + d0]);
            qa[ks][2] = to_tf32(q[off0 + d0 + 4]);
            qa[ks][3] = to_tf32(q[off8 + d0 + 4]);
        }
    }

    float oacc[8][4] = {};
    float mi0 = -1e30f, mi1 = -1e30f;
    float li0 = 0.f,    li1 = 0.f;

    for (int l0 = 0; l0 < LCTX; l0 += 64) {
        __syncthreads();                       // K/V buffers free
        // Load K,V tiles (coalesced float4), convert to tf32, STS.128
        #pragma unroll
        for (int r = 0; r < 4; r++) {
            const int lin = tid + r * 256;
            const int key = lin >> 4;          // 0..63
            const int d4  = (lin & 15) * 4;
            const size_t go = (size_t)((l0 + key) * BATCHN + b) * DMODEL + h * KDIM + d4;
            const float4 tk = *(const float4*)&k[go];
            const float4 tv = *(const float4*)&v[go];
            const uint4 uk = make_uint4(to_tf32(tk.x), to_tf32(tk.y), to_tf32(tk.z), to_tf32(tk.w));
            const uint4 uv = make_uint4(to_tf32(tv.x), to_tf32(tv.y), to_tf32(tv.z), to_tf32(tv.w));
            *(uint4*)&Ks[key][d4] = uk;
            *(uint4*)&Vs[key][d4] = uv;
        }
        __syncthreads();

        // S = Q K^T : warp computes 16 rows x 64 keys (8 n-frags)
        float sc[8][4];
        #pragma unroll
        for (int nt = 0; nt < 8; nt++) { sc[nt][0]=0.f; sc[nt][1]=0.f; sc[nt][2]=0.f; sc[nt][3]=0.f; }
        #pragma unroll
        for (int ks = 0; ks < 8; ks++) {
            const int kb = ks * 8 + t;
            #pragma unroll
            for (int nt = 0; nt < 8; nt++) {
                const uint32_t b0 = Ks[nt * 8 + g][kb];
                const uint32_t b1 = Ks[nt * 8 + g][kb + 4];
                mma_tf32(sc[nt][0], sc[nt][1], sc[nt][2], sc[nt][3],
                         qa[ks][0], qa[ks][1], qa[ks][2], qa[ks][3], b0, b1);
            }
        }

        // scale + mask, row-wise online softmax (rows row0 and row0+8)
        float ml0 = -1e30f, ml1 = -1e30f;
        #pragma unroll
        for (int nt = 0; nt < 8; nt++) {
            const int col = l0 + nt * 8 + 2 * t;
            const float2 m01 = *(const float2*)&mask[(size_t)row0       * LCTX + col];
            const float2 m23 = *(const float2*)&mask[(size_t)(row0 + 8) * LCTX + col];
            sc[nt][0] = fmaf(sc[nt][0], 0.125f, m01.x);
            sc[nt][1] = fmaf(sc[nt][1], 0.125f, m01.y);
            sc[nt][2] = fmaf(sc[nt][2], 0.125f, m23.x);
            sc[nt][3] = fmaf(sc[nt][3], 0.125f, m23.y);
            ml0 = fmaxf(ml0, fmaxf(sc[nt][0], sc[nt][1]));
            ml1 = fmaxf(ml1, fmaxf(sc[nt][2], sc[nt][3]));
        }
        ml0 = fmaxf(ml0, __shfl_xor_sync(FULL, ml0, 1));
        ml0 = fmaxf(ml0, __shfl_xor_sync(FULL, ml0, 2));
        ml1 = fmaxf(ml1, __shfl_xor_sync(FULL, ml1, 1));
        ml1 = fmaxf(ml1, __shfl_xor_sync(FULL, ml1, 2));

        const float mn0 = fmaxf(mi0, ml0);
        const float mn1 = fmaxf(mi1, ml1);
        const float c0  = __expf(mi0 - mn0);
        const float c1  = __expf(mi1 - mn1);
        mi0 = mn0; mi1 = mn1;

        float rs0 = 0.f, rs1 = 0.f;
        #pragma unroll
        for (int nt = 0; nt < 8; nt++) {
            // exp, round to tf32; the SAME rounded values feed l_i and PV
            const float p0 = __uint_as_float(to_tf32(__expf(sc[nt][0] - mn0)));
            const float p1 = __uint_as_float(to_tf32(__expf(sc[nt][1] - mn0)));
            const float p2 = __uint_as_float(to_tf32(__expf(sc[nt][2] - mn1)));
            const float p3 = __uint_as_float(to_tf32(__expf(sc[nt][3] - mn1)));
            sc[nt][0] = p0; sc[nt][1] = p1; sc[nt][2] = p2; sc[nt][3] = p3;
            rs0 += p0 + p1;
            rs1 += p2 + p3;
        }
        rs0 += __shfl_xor_sync(FULL, rs0, 1);
        rs0 += __shfl_xor_sync(FULL, rs0, 2);
        rs1 += __shfl_xor_sync(FULL, rs1, 1);
        rs1 += __shfl_xor_sync(FULL, rs1, 2);
        li0 = li0 * c0 + rs0;
        li1 = li1 * c1 + rs1;

        // rescale O
        #pragma unroll
        for (int nt = 0; nt < 8; nt++) {
            oacc[nt][0] *= c0; oacc[nt][1] *= c0;
            oacc[nt][2] *= c1; oacc[nt][3] *= c1;
        }

        // O += P V : permute P (C-layout) into A-fragments via shfl, mma vs Vs
        const int src0 = (lane & ~3) | (t >> 1);
        const int sel  = t & 1;
        #pragma unroll
        for (int ks = 0; ks < 8; ks++) {
            const float v00 = __shfl_sync(FULL, sc[ks][0], src0);
            const float v01 = __shfl_sync(FULL, sc[ks][1], src0);
            const float v20 = __shfl_sync(FULL, sc[ks][2], src0);
            const float v31 = __shfl_sync(FULL, sc[ks][3], src0);
            const float w00 = __shfl_sync(FULL, sc[ks][0], src0 + 2);
            const float w01 = __shfl_sync(FULL, sc[ks][1], src0 + 2);
            const float w20 = __shfl_sync(FULL, sc[ks][2], src0 + 2);
            const float w31 = __shfl_sync(FULL, sc[ks][3], src0 + 2);
            const uint32_t a0 = __float_as_uint(sel ? v01 : v00);
            const uint32_t a1 = __float_as_uint(sel ? v31 : v20);
            const uint32_t a2 = __float_as_uint(sel ? w01 : w00);
            const uint32_t a3 = __float_as_uint(sel ? w31 : w20);
            const int kr = ks * 8 + t;
            #pragma unroll
            for (int nt = 0; nt < 8; nt++) {
                const uint32_t b0 = Vs[kr    ][nt * 8 + g];
                const uint32_t b1 = Vs[kr + 4][nt * 8 + g];
                mma_tf32(oacc[nt][0], oacc[nt][1], oacc[nt][2], oacc[nt][3],
                         a0, a1, a2, a3, b0, b1);
            }
        }
    }

    // normalize + write out
    const float inv0 = 1.f / li0;
    const float inv1 = 1.f / li1;
    const size_t oo0 = (size_t)(row0       * BATCHN + b) * DMODEL + h * KDIM;
    const size_t oo8 = (size_t)((row0 + 8) * BATCHN + b) * DMODEL + h * KDIM;
    #pragma unroll
    for (int nt = 0; nt < 8; nt++) {
        const int col = nt * 8 + 2 * t;
        *(float2*)&av[oo0 + col] = make_float2(oacc[nt][0] * inv0, oacc[nt][1] * inv0);
        *(float2*)&av[oo8 + col] = make_float2(oacc[nt][2] * inv1, oacc[nt][3] * inv1);
    }
}

// ---------------------------------------------------------------------------
// Fused residual + LayerNorm
// ---------------------------------------------------------------------------
__global__ __launch_bounds__(256) void ln_kernel(
    const float* __restrict__ a, const float* __restrict__ r,
    const float* __restrict__ gamma, const float* __restrict__ beta,
    float* __restrict__ out)
{
    __shared__ float red[2][8];
    const int row = blockIdx.x;
    const int tid = threadIdx.x;
    const float* pa = a + (size_t)row * DMODEL;
    const float* pr = r + (size_t)row * DMODEL;

    float vl[4];
    float s = 0.f, s2 = 0.f;
    #pragma unroll
    for (int i = 0; i < 4; i++) {
        const int c = tid + i * 256;
        const float xv = pa[c] + pr[c];
        vl[i] = xv;
        s += xv;
        s2 = fmaf(xv, xv, s2);
    }
    #pragma unroll
    for (int m = 16; m > 0; m >>= 1) {
        s  += __shfl_xor_sync(0xffffffffu, s,  m);
        s2 += __shfl_xor_sync(0xffffffffu, s2, m);
    }
    if ((tid & 31) == 0) { red[0][tid >> 5] = s; red[1][tid >> 5] = s2; }
    __syncthreads();
    if (tid == 0) {
        float a0 = 0.f, b0 = 0.f;
        #pragma unroll
        for (int ww = 0; ww < 8; ww++) { a0 += red[0][ww]; b0 += red[1][ww]; }
        red[0][0] = a0; red[1][0] = b0;
    }
    __syncthreads();
    const float mu  = red[0][0] * (1.f / DMODEL);
    const float var = red[1][0] * (1.f / DMODEL) - mu * mu;
    const float inv = rsqrtf(var + LN_EPS);

    float* po = out + (size_t)row * DMODEL;
    #pragma unroll
    for (int i = 0; i < 4; i++) {
        const int c = tid + i * 256;
        po[c] = (vl[i] - mu) * inv * gamma[c] + beta[c];
    }
}

// ---------------------------------------------------------------------------
// Launch
// ---------------------------------------------------------------------------
extern "C" void kernel_launch(void* const* d_in, const int* in_sizes, int n_in,
                              void* d_out, int out_size)
{
    const float* x    = (const float*)d_in[0];
    const float* mask = (const float*)d_in[1];
    const float* mem  = (const float*)d_in[2];
    const float* wq   = (const float*)d_in[4];
    const float* wk   = (const float*)d_in[5];
    const float* wv   = (const float*)d_in[6];
    const float* wc   = (const float*)d_in[7];
    const float* w1   = (const float*)d_in[8];
    const float* b1   = (const float*)d_in[9];
    const float* w2   = (const float*)d_in[10];
    const float* b2   = (const float*)d_in[11];
    const float* g1   = (const float*)d_in[12];
    const float* be1  = (const float*)d_in[13];
    const float* g2   = (const float*)d_in[14];
    const float* be2  = (const float*)d_in[15];
    float* out = (float*)d_out;

    float *q, *k, *v, *avp, *u0, *u, *hh, *z;
    cudaGetSymbolAddress((void**)&q,   g_q);
    cudaGetSymbolAddress((void**)&k,   g_k);
    cudaGetSymbolAddress((void**)&v,   g_v);
    cudaGetSymbolAddress((void**)&avp, g_av);
    cudaGetSymbolAddress((void**)&u0,  g_u0);
    cudaGetSymbolAddress((void**)&u,   g_u);
    cudaGetSymbolAddress((void**)&hh,  g_h);
    cudaGetSymbolAddress((void**)&z,   g_z);

    const dim3 blk(256);
    const int splitKV = MEMLEN * SEQ * BATCHN;

    gemm_tf32<0><<<dim3(DMODEL/128, NTOK/128), blk>>>(x,   x, NTOK,    wq, nullptr, q, NTOK, DMODEL, DMODEL);
    gemm_tf32<0><<<dim3(DMODEL/128, NKV /128), blk>>>(mem, x, splitKV, wk, nullptr, k, NKV,  DMODEL, DMODEL);
    gemm_tf32<0><<<dim3(DMODEL/128, NKV /128), blk>>>(mem, x, splitKV, wv, nullptr, v, NKV,  DMODEL, DMODEL);

    attn_mma<<<dim3(SEQ/128, NH*BATCHN), blk>>>(q, k, v, mask, avp);

    gemm_tf32<0><<<dim3(DMODEL/128, NTOK/128), blk>>>(avp, avp, NTOK, wc, nullptr, u0, NTOK, DMODEL, DMODEL);
    ln_kernel<<<NTOK, blk>>>(u0, x, g1, be1, u);

    gemm_tf32<2><<<dim3(MFF   /128, NTOK/128), blk>>>(u,  u,  NTOK, w1, b1, hh, NTOK, MFF,    DMODEL);
    gemm_tf32<1><<<dim3(DMODEL/128, NTOK/128), blk>>>(hh, hh, NTOK, w2, b2, z,  NTOK, DMODEL, MFF);

    ln_kernel<<<NTOK, blk>>>(z, u, g2, be2, out);
}